// round 17
// baseline (speedup 1.0000x reference)
#include <cuda_runtime.h>
#include <math.h>
#include <stdint.h>

// ---------------------------------------------------------------------------
// AdaptivePatchEmbedding — B=128,C=32,S=336 -> N=4096, R=7, TARGET=6, D=512
// Straight-through gumbel == one-hot: compute only selected expert per region.
// Unique patch rows per region: P=8 ->6, P=16/24 ->2, P=48 ->1.
// TWO launches: router (pe table + compaction into 28 (e,r) buckets) ->
// persistent fused embed with R16 machinery (per-expert cursor, 24-row
// super-chunks, 2 halves per fill, elided barriers) over a bucket-partitioned
// chunk space: every chunk has uniform r, so the epilogue hoists the
// positional-embedding load t-outer (1 pe LDG per t, reused across rows).
// ---------------------------------------------------------------------------

#define NB 28                 // 4 experts x 7 region slots
#define XP_ELEMS 88080384LL   // 4096 * 42 * 512

__device__ int   g_cnt[NB];     // zero at module load; embed resets at end
__device__ int   g_cur[4];
__device__ int   g_done;
__device__ int   g_lists[NB * 4096];   // bucket entries = sequence index n
__device__ float g_pe[42 * 512];

// --------------------------- stage 1: router + pe table ---------------------
__global__ void __launch_bounds__(64) router_kernel(
    const float* __restrict__ x,  const float* __restrict__ un,
    const float* __restrict__ W1, const float* __restrict__ b1,
    const float* __restrict__ W2, const float* __restrict__ b2,
    float* __restrict__ out, int write_mode)
{
    __shared__ float W1s[48 * 64];
    __shared__ float W2s[256];
    __shared__ float b1s[64];
    int tid = threadIdx.x;
    int region = blockIdx.x * 64 + tid;      // grid = 448 -> exactly 28672

    // pe table: one dim-pair per thread, first 10752 threads; fp64 exp
    // latency hides under the MLP below.
    if (region < 10752) {
        int pos = region >> 8;               // [0,42)
        int tp  = region & 255;              // dim pair [0,256)
        double dv = exp((double)(2 * tp) * -(log(10000.0) / 512.0));
        float ang = (float)((double)pos * dv);
        float2 sc = make_float2(sinf(ang), cosf(ang));
        *(float2*)&g_pe[pos * 512 + 2 * tp] = sc;
    }

    for (int i = tid; i < 768; i += 64) ((float4*)W1s)[i] = ((const float4*)W1)[i];
    ((float4*)W2s)[tid] = ((const float4*)W2)[tid];
    b1s[tid] = b1[tid];
    __syncthreads();

    int n = region / 7, r = region - n * 7;

    float xr[48];
    const float4* xp = (const float4*)x + n * 84 + r * 12;
#pragma unroll
    for (int v = 0; v < 12; v++) {
        float4 t4 = xp[v];
        xr[4*v+0] = t4.x; xr[4*v+1] = t4.y; xr[4*v+2] = t4.z; xr[4*v+3] = t4.w;
    }

    float lg0 = b2[0], lg1 = b2[1], lg2 = b2[2], lg3 = b2[3];
#pragma unroll 2
    for (int k = 0; k < 64; k++) {
        float s = b1s[k];
#pragma unroll
        for (int j = 0; j < 48; j++) s = fmaf(xr[j], W1s[j * 64 + k], s);
        s = fmaxf(s, 0.0f);
        lg0 = fmaf(s, W2s[k*4+0], lg0);
        lg1 = fmaf(s, W2s[k*4+1], lg1);
        lg2 = fmaf(s, W2s[k*4+2], lg2);
        lg3 = fmaf(s, W2s[k*4+3], lg3);
    }

    const float* up = un + (long long)region * 4;
    float z0 = lg0 - logf(-logf(up[0] + 1e-10f) + 1e-10f);
    float z1 = lg1 - logf(-logf(up[1] + 1e-10f) + 1e-10f);
    float z2 = lg2 - logf(-logf(up[2] + 1e-10f) + 1e-10f);
    float z3 = lg3 - logf(-logf(up[3] + 1e-10f) + 1e-10f);

    int e = 0; float best = z0;              // first-max semantics like jnp.argmax
    if (z1 > best) { best = z1; e = 1; }
    if (z2 > best) { best = z2; e = 2; }
    if (z3 > best) { best = z3; e = 3; }

    int bidx = e * 7 + r;
    int slot = atomicAdd(&g_cnt[bidx], 1);
    g_lists[bidx * 4096 + slot] = n;

    if (write_mode >= 2) out[XP_ELEMS + 1 + (long long)r * 4096 + n] = (float)e;
    if (write_mode >= 1 && region == 0) out[XP_ELEMS] = 32.0f;
}

// --------------------------- stage 2: persistent fused embed ----------------
// SUPER-CHUNK = 24 unique rows (RPB2 regions, uniform r), 2 halves of 12 rows.
// Thread (tx in [0,128), ty in {0,1}) owns 6 rows x 4 cols per half.
// K = 7-48/P, U = ceil(6/K), RPB2 = 24/U, RH = 12/U, RL = 6/U.
// One cursor per expert over a bucket-partitioned chunk space.
template<int P, bool WSM>
__device__ __forceinline__ void embed_expert(
    const float4* __restrict__ x4, const float4* __restrict__ W4,
    float4* __restrict__ out4, float* Wsm, float* xrs, int* ibuf)
{
    constexpr int E    = (P == 8) ? 0 : (P == 16) ? 1 : (P == 24) ? 2 : 3;
    constexpr int K    = 7 - 48 / P;
    constexpr int U    = (6 + K - 1) / K;
    constexpr int RPB2 = 24 / U;       // regions per super-chunk
    constexpr int RH   = 12 / U;       // regions per half
    constexpr int RL   = 6 / U;        // regions per half per ty
    constexpr int HOFF = RH * 48;      // xrs float offset of half 1

    const int tid = threadIdx.x;

    // bucket chunk counts + total (block-uniform, registers)
    int cntb[7], nchb[7];
    int TC = 0;
#pragma unroll
    for (int r = 0; r < 7; r++) {
        cntb[r] = g_cnt[E * 7 + r];
        nchb[r] = (cntb[r] + RPB2 - 1) / RPB2;
        TC += nchb[r];
    }

    if (WSM) {
        for (int i = tid; i < P * 128; i += 256)
            ((float4*)Wsm)[i] = W4[i];
    }
    const int tx = tid & 127, ty = tid >> 7;

    int aoff[6];
#pragma unroll
    for (int rr = 0; rr < 6; rr++) {
        int row = ty * 6 + rr;
        aoff[rr] = (row / U) * 48 + (row % U) * P;   // multiple of 4 floats
    }

    for (;;) {
        if (tid == 0) ibuf[31] = atomicAdd(&g_cur[E], 1);
        __syncthreads();                 // also orders prev compute vs next fill
        int c = ibuf[31];
        if (c >= TC) break;

        // chunk -> (bucket r, local chunk rel): uniform 7-step walk
        int r = 0, rel = c;
#pragma unroll
        for (int i = 0; i < 6; i++) {
            if (rel >= nchb[r]) { rel -= nchb[r]; r++; }
        }
        const int cnt  = cntb[r];
        const int base = rel * RPB2;
        const int nval = min(RPB2, cnt - base);
        const int* lst = g_lists + (E * 7 + r) * 4096 + base;

        if (tid < nval) ibuf[tid] = lst[tid];
        __syncthreads();

        for (int i = tid; i < nval * 12; i += 256) {
            int reg = i / 12, v = i - reg * 12;
            int n = ibuf[reg];
            ((float4*)xrs)[reg * 12 + v] = __ldg(&x4[n * 84 + r * 12 + v]);
        }
        __syncthreads();

#pragma unroll 1
        for (int h = 0; h < 2; h++) {    // two 12-row halves, NOT unrolled
            const int regbase = h * RH;
            if (regbase >= nval) break;  // block-uniform
            const float* xh = xrs + h * HOFF;

            float4 acc[6];
#pragma unroll
            for (int i = 0; i < 6; i++) acc[i] = make_float4(0.f, 0.f, 0.f, 0.f);

#pragma unroll
            for (int k = 0; k < P; k += 4) {
                float4 b0 = WSM ? ((const float4*)Wsm)[(k + 0) * 128 + tx]
                                : __ldg(&W4[(k + 0) * 128 + tx]);
                float4 b1 = WSM ? ((const float4*)Wsm)[(k + 1) * 128 + tx]
                                : __ldg(&W4[(k + 1) * 128 + tx]);
                float4 b2 = WSM ? ((const float4*)Wsm)[(k + 2) * 128 + tx]
                                : __ldg(&W4[(k + 2) * 128 + tx]);
                float4 b3 = WSM ? ((const float4*)Wsm)[(k + 3) * 128 + tx]
                                : __ldg(&W4[(k + 3) * 128 + tx]);
#pragma unroll
                for (int rr = 0; rr < 6; rr++) {
                    float4 a = *(const float4*)&xh[aoff[rr] + k]; // 1 LDS.128
                    acc[rr].x = fmaf(a.x, b0.x, acc[rr].x);
                    acc[rr].y = fmaf(a.x, b0.y, acc[rr].y);
                    acc[rr].z = fmaf(a.x, b0.z, acc[rr].z);
                    acc[rr].w = fmaf(a.x, b0.w, acc[rr].w);
                    acc[rr].x = fmaf(a.y, b1.x, acc[rr].x);
                    acc[rr].y = fmaf(a.y, b1.y, acc[rr].y);
                    acc[rr].z = fmaf(a.y, b1.z, acc[rr].z);
                    acc[rr].w = fmaf(a.y, b1.w, acc[rr].w);
                    acc[rr].x = fmaf(a.z, b2.x, acc[rr].x);
                    acc[rr].y = fmaf(a.z, b2.y, acc[rr].y);
                    acc[rr].z = fmaf(a.z, b2.z, acc[rr].z);
                    acc[rr].w = fmaf(a.z, b2.w, acc[rr].w);
                    acc[rr].x = fmaf(a.w, b3.x, acc[rr].x);
                    acc[rr].y = fmaf(a.w, b3.y, acc[rr].y);
                    acc[rr].z = fmaf(a.w, b3.z, acc[rr].z);
                    acc[rr].w = fmaf(a.w, b3.w, acc[rr].w);
                }
            }

            // epilogue: t-outer, pe loaded ONCE per t (uniform r per chunk)
            const float4* pe4 = (const float4*)g_pe;
#pragma unroll
            for (int t = 0; t < 6; t++) {
                const int q   = t / K;                    // compile-time
                const int pos = r * 6 + t;
                float4 p = __ldg(&pe4[pos * 128 + tx]);
#pragma unroll
                for (int rl = 0; rl < RL; rl++) {
                    int rr  = rl * U + q;                 // acc row
                    int reg = regbase + ty * RL + rl;     // region in chunk
                    if (reg >= nval) continue;
                    int n = ibuf[reg];
                    float4 v = make_float4(acc[rr].x + p.x, acc[rr].y + p.y,
                                           acc[rr].z + p.z, acc[rr].w + p.w);
                    __stcs(&out4[(long long)n * 5376 + pos * 128 + tx], v);
                }
            }
        }
        // no end barrier: next iteration's post-atomic barrier orders reuse
    }
    __syncthreads();   // phase separation before Wsm/xrs/ibuf reuse
}

__global__ void __launch_bounds__(256, 4) embed_fused_kernel(
    const float4* __restrict__ x4,
    const float4* __restrict__ We0, const float4* __restrict__ We1,
    const float4* __restrict__ We2, const float4* __restrict__ We3,
    float4* __restrict__ out4)
{
    extern __shared__ float sm[];
    float* Wsm = sm;                       // up to 24*512 floats
    float* xrs = sm + 24 * 512;            // 24*48 floats (super-chunk)
    int*   ibuf = (int*)(xrs + 24 * 48);   // 32 ints

    embed_expert<48, false>(x4, We3, out4, Wsm, xrs, ibuf);
    embed_expert<24, true >(x4, We2, out4, Wsm, xrs, ibuf);
    embed_expert<16, true >(x4, We1, out4, Wsm, xrs, ibuf);
    embed_expert< 8, true >(x4, We0, out4, Wsm, xrs, ibuf);

    // last block out resets routing state for the next graph replay
    if (threadIdx.x == 0) {
        int d = atomicAdd(&g_done, 1);
        if (d == (int)gridDim.x - 1) {
#pragma unroll
            for (int i = 0; i < NB; i++) g_cnt[i] = 0;
            g_cur[0] = 0; g_cur[1] = 0; g_cur[2] = 0; g_cur[3] = 0;
            g_done = 0;
        }
    }
}

// --------------------------- launch ------------------------------------------
extern "C" void kernel_launch(void* const* d_in, const int* in_sizes, int n_in,
                              void* d_out, int out_size) {
    const float* x  = (const float*)d_in[0];
    const float* un = (const float*)d_in[1];
    const float* W1 = (const float*)d_in[2];
    const float* b1 = (const float*)d_in[3];
    const float* W2 = (const float*)d_in[4];
    const float* b2 = (const float*)d_in[5];
    const float4* We0 = (const float4*)d_in[6];
    const float4* We1 = (const float4*)d_in[7];
    const float4* We2 = (const float4*)d_in[8];
    const float4* We3 = (const float4*)d_in[9];
    float*  out  = (float*)d_out;
    float4* out4 = (float4*)d_out;
    const float4* x4 = (const float4*)d_in[0];

    int write_mode = 0;
    if ((long long)out_size >= XP_ELEMS + 1 + 28672) write_mode = 2;
    else if ((long long)out_size >= XP_ELEMS + 1)    write_mode = 1;

    const int SMEM = (24 * 512 + 24 * 48) * 4 + 128;   // 53888 bytes
    cudaFuncSetAttribute(embed_fused_kernel,
                         cudaFuncAttributeMaxDynamicSharedMemorySize, SMEM);

    router_kernel<<<448, 64>>>(x, un, W1, b1, W2, b2, out, write_mode);
    embed_fused_kernel<<<592, 256, SMEM>>>(x4, We0, We1, We2, We3, out4);
    (void)in_sizes; (void)n_in;
}